// round 2
// baseline (speedup 1.0000x reference)
#include <cuda_runtime.h>

#define N_ 50000
#define K_ 32
#define D_ 128
#define EPS_ 1e-12f
#define WARPS_PER_BLOCK 8

__device__ double g_loss_accum;

__global__ void snl_zero_kernel() {
    g_loss_accum = 0.0;
}

__global__ __launch_bounds__(WARPS_PER_BLOCK * 32)
void snl_main_kernel(const float* __restrict__ emb,
                     const float* __restrict__ p,
                     const int* __restrict__ anchor,
                     float* __restrict__ out_q /* out + 1 */) {
    __shared__ float yi_s[WARPS_PER_BLOCK][D_];
    __shared__ double loss_s[WARPS_PER_BLOCK];

    const int warp = threadIdx.x >> 5;
    const int lane = threadIdx.x & 31;
    const int i = blockIdx.x * WARPS_PER_BLOCK + warp;
    bool active = (i < N_);

    float d2 = 0.0f;
    float pv = 0.0f;

    if (active) {
        // cooperative load of yi into shared: 32 lanes x float4 = 512B
        const float4* yi4 = reinterpret_cast<const float4*>(emb + (size_t)i * D_);
        reinterpret_cast<float4*>(yi_s[warp])[lane] = yi4[lane];
    }
    __syncwarp();

    if (active) {
        int j = anchor[(size_t)i * K_ + lane];
        // defensive clamp: a bad index becomes wrong-answer (rel_err), not a crash
        j = max(0, min(j, N_ - 1));
        pv = p[(size_t)i * K_ + lane];
        const float4* yj4 = reinterpret_cast<const float4*>(emb + (size_t)j * D_);
        const float4* yis = reinterpret_cast<const float4*>(yi_s[warp]);
        #pragma unroll
        for (int t = 0; t < D_ / 4; t++) {
            float4 a = yis[t];
            float4 b = yj4[t];
            float dx = a.x - b.x;
            float dy = a.y - b.y;
            float dz = a.z - b.z;
            float dw = a.w - b.w;
            d2 = fmaf(dx, dx, d2);
            d2 = fmaf(dy, dy, d2);
            d2 = fmaf(dz, dz, d2);
            d2 = fmaf(dw, dw, d2);
        }
    }

    // softmax over K=32 lanes of s = -d2
    float s = -d2;
    float m = s;
    #pragma unroll
    for (int o = 16; o; o >>= 1) m = fmaxf(m, __shfl_xor_sync(0xffffffffu, m, o));
    float e = __expf(s - m);
    float sum = e;
    #pragma unroll
    for (int o = 16; o; o >>= 1) sum += __shfl_xor_sync(0xffffffffu, sum, o);
    float lse = m + __logf(sum);
    float logq = s - lse;
    float q = __expf(logq);

    float contrib = 0.0f;
    if (active) {
        out_q[(size_t)i * K_ + lane] = q;
        contrib = pv * (__logf(pv + EPS_) - logq);
    }
    // warp-reduce loss contribution
    #pragma unroll
    for (int o = 16; o; o >>= 1) contrib += __shfl_xor_sync(0xffffffffu, contrib, o);
    if (lane == 0) loss_s[warp] = (double)contrib;
    __syncthreads();

    if (warp == 0 && lane == 0) {
        double blk = 0.0;
        #pragma unroll
        for (int w = 0; w < WARPS_PER_BLOCK; w++) blk += loss_s[w];
        atomicAdd(&g_loss_accum, blk);
    }
}

__global__ void snl_finalize_kernel(float* __restrict__ out) {
    out[0] = (float)(g_loss_accum / (double)N_);
}

extern "C" void kernel_launch(void* const* d_in, const int* in_sizes, int n_in,
                              void* d_out, int out_size) {
    const float* emb    = (const float*)d_in[0];  // output_embedding [N, D] f32
    const float* p      = (const float*)d_in[1];  // input_similarity [N, K] f32
    const int*   anchor = (const int*)d_in[2];    // anchor_idx [N, K] int32 (JAX x64 off)
    float* out = (float*)d_out;                   // [0]=loss, [1..]=q row-major

    snl_zero_kernel<<<1, 1>>>();
    const int blocks = (N_ + WARPS_PER_BLOCK - 1) / WARPS_PER_BLOCK;
    snl_main_kernel<<<blocks, WARPS_PER_BLOCK * 32>>>(emb, p, anchor, out + 1);
    snl_finalize_kernel<<<1, 1>>>(out);
}

// round 3
// speedup vs baseline: 2.6290x; 2.6290x over previous
#include <cuda_runtime.h>

#define N_ 50000
#define K_ 32
#define D_ 128
#define EPS_ 1e-12f
#define WARPS_PER_BLOCK 8
#define NBLOCKS_ ((N_ + WARPS_PER_BLOCK - 1) / WARPS_PER_BLOCK)   // 6250

__device__ double g_block_partials[NBLOCKS_];

__global__ __launch_bounds__(WARPS_PER_BLOCK * 32)
void snl_main_kernel(const float* __restrict__ emb,
                     const float* __restrict__ p,
                     const int* __restrict__ anchor,
                     float* __restrict__ out_q /* out + 1 */) {
    __shared__ double loss_s[WARPS_PER_BLOCK];

    const int warp = threadIdx.x >> 5;
    const int lane = threadIdx.x & 31;
    const int i = blockIdx.x * WARPS_PER_BLOCK + warp;   // 6250*8 == 50000 exactly

    // yi: lane t holds elements [4t, 4t+4) of row i  (coalesced 512B load)
    const float4 a = reinterpret_cast<const float4*>(emb + (size_t)i * D_)[lane];

    // my anchor index + p value (lane k owns anchor k)
    int j_mine = anchor[(size_t)i * K_ + lane];
    j_mine = max(0, min(j_mine, N_ - 1));                // defensive clamp
    const float pv = p[(size_t)i * K_ + lane];

    float myd2 = 0.0f;   // lane r will hold d2 for anchor r

    #pragma unroll 8
    for (int r = 0; r < K_; r++) {
        const int jr = __shfl_sync(0xffffffffu, j_mine, r);
        // cooperative, fully coalesced 512B row load: lane t takes float4 t
        const float4 b = reinterpret_cast<const float4*>(emb + (size_t)jr * D_)[lane];
        float dx = a.x - b.x;
        float dy = a.y - b.y;
        float dz = a.z - b.z;
        float dw = a.w - b.w;
        float part = dx * dx;
        part = fmaf(dy, dy, part);
        part = fmaf(dz, dz, part);
        part = fmaf(dw, dw, part);
        // butterfly sum across lanes -> full d2 for anchor r in every lane
        #pragma unroll
        for (int o = 16; o; o >>= 1) part += __shfl_xor_sync(0xffffffffu, part, o);
        if (lane == r) myd2 = part;
    }

    // softmax over K=32 lanes of s = -d2
    const float s = -myd2;
    float m = s;
    #pragma unroll
    for (int o = 16; o; o >>= 1) m = fmaxf(m, __shfl_xor_sync(0xffffffffu, m, o));
    const float e = __expf(s - m);
    float sum = e;
    #pragma unroll
    for (int o = 16; o; o >>= 1) sum += __shfl_xor_sync(0xffffffffu, sum, o);
    const float lse = m + __logf(sum);
    const float logq = s - lse;
    const float q = __expf(logq);

    out_q[(size_t)i * K_ + lane] = q;

    // KL contribution, warp-reduced
    float contrib = pv * (__logf(pv + EPS_) - logq);
    #pragma unroll
    for (int o = 16; o; o >>= 1) contrib += __shfl_xor_sync(0xffffffffu, contrib, o);
    if (lane == 0) loss_s[warp] = (double)contrib;
    __syncthreads();

    if (warp == 0 && lane == 0) {
        double blk = 0.0;
        #pragma unroll
        for (int w = 0; w < WARPS_PER_BLOCK; w++) blk += loss_s[w];
        g_block_partials[blockIdx.x] = blk;   // overwritten every run: no init kernel needed
    }
}

__global__ __launch_bounds__(512)
void snl_finalize_kernel(float* __restrict__ out) {
    __shared__ double red_s[512];
    double acc = 0.0;
    for (int b = threadIdx.x; b < NBLOCKS_; b += 512)
        acc += g_block_partials[b];
    red_s[threadIdx.x] = acc;
    __syncthreads();
    for (int o = 256; o; o >>= 1) {
        if (threadIdx.x < o) red_s[threadIdx.x] += red_s[threadIdx.x + o];
        __syncthreads();
    }
    if (threadIdx.x == 0)
        out[0] = (float)(red_s[0] / (double)N_);
}

extern "C" void kernel_launch(void* const* d_in, const int* in_sizes, int n_in,
                              void* d_out, int out_size) {
    const float* emb    = (const float*)d_in[0];  // output_embedding [N, D] f32
    const float* p      = (const float*)d_in[1];  // input_similarity [N, K] f32
    const int*   anchor = (const int*)d_in[2];    // anchor_idx [N, K] int32
    float* out = (float*)d_out;                   // [0]=loss, [1..]=q row-major

    snl_main_kernel<<<NBLOCKS_, WARPS_PER_BLOCK * 32>>>(emb, p, anchor, out + 1);
    snl_finalize_kernel<<<1, 512>>>(out);
}

// round 4
// speedup vs baseline: 2.6558x; 1.0102x over previous
#include <cuda_runtime.h>

#define N_ 50000
#define K_ 32
#define D_ 128
#define EPS_ 1e-12f
#define WARPS_PER_BLOCK 8
#define THREADS_ (WARPS_PER_BLOCK * 32)
#define NBLOCKS_ ((N_ + WARPS_PER_BLOCK - 1) / WARPS_PER_BLOCK)   // 6250

__device__ double   g_block_partials[NBLOCKS_];
__device__ unsigned g_ticket = 0;   // returns to 0 at the end of every run (graph-replay safe)

__global__ __launch_bounds__(THREADS_)
void snl_main_kernel(const float* __restrict__ emb,
                     const float* __restrict__ p,
                     const int* __restrict__ anchor,
                     float* __restrict__ out /* [0]=loss, [1..]=q */) {
    __shared__ double loss_s[WARPS_PER_BLOCK];
    __shared__ double red_s[THREADS_];
    __shared__ bool   is_last;

    const int warp = threadIdx.x >> 5;
    const int lane = threadIdx.x & 31;
    const int i = blockIdx.x * WARPS_PER_BLOCK + warp;   // 6250*8 == 50000 exactly
    float* __restrict__ out_q = out + 1;

    // yi: lane t holds elements [4t, 4t+4) of row i  (coalesced 512B load)
    const float4 a = reinterpret_cast<const float4*>(emb + (size_t)i * D_)[lane];

    // my anchor index + p value (lane k owns anchor k)
    int j_mine = anchor[(size_t)i * K_ + lane];
    j_mine = max(0, min(j_mine, N_ - 1));                // defensive clamp
    const float pv = p[(size_t)i * K_ + lane];

    float myd2 = 0.0f;   // lane r ends with d2 for anchor r

    #pragma unroll 8
    for (int r = 0; r < K_; r++) {
        const int jr = __shfl_sync(0xffffffffu, j_mine, r);
        // cooperative, fully coalesced 512B row load: lane t takes float4 t
        const float4 b = reinterpret_cast<const float4*>(emb + (size_t)jr * D_)[lane];
        float dx = a.x - b.x;
        float dy = a.y - b.y;
        float dz = a.z - b.z;
        float dw = a.w - b.w;
        float part = dx * dx;
        part = fmaf(dy, dy, part);
        part = fmaf(dz, dz, part);
        part = fmaf(dw, dw, part);
        // butterfly sum across lanes -> full d2 for anchor r in every lane
        #pragma unroll
        for (int o = 16; o; o >>= 1) part += __shfl_xor_sync(0xffffffffu, part, o);
        if (lane == r) myd2 = part;
    }

    // softmax over K=32 lanes of s = -d2
    const float s = -myd2;
    float m = s;
    #pragma unroll
    for (int o = 16; o; o >>= 1) m = fmaxf(m, __shfl_xor_sync(0xffffffffu, m, o));
    const float e = __expf(s - m);
    float sum = e;
    #pragma unroll
    for (int o = 16; o; o >>= 1) sum += __shfl_xor_sync(0xffffffffu, sum, o);
    const float lse = m + __logf(sum);
    const float logq = s - lse;
    const float q = __expf(logq);

    out_q[(size_t)i * K_ + lane] = q;

    // KL contribution, warp-reduced
    float contrib = pv * (__logf(pv + EPS_) - logq);
    #pragma unroll
    for (int o = 16; o; o >>= 1) contrib += __shfl_xor_sync(0xffffffffu, contrib, o);
    if (lane == 0) loss_s[warp] = (double)contrib;
    __syncthreads();

    // block partial -> global, take a ticket; last block does the final sum
    if (threadIdx.x == 0) {
        double blk = 0.0;
        #pragma unroll
        for (int w = 0; w < WARPS_PER_BLOCK; w++) blk += loss_s[w];
        g_block_partials[blockIdx.x] = blk;
        __threadfence();
        unsigned t = atomicAdd(&g_ticket, 1u);
        is_last = (t == (unsigned)(NBLOCKS_ - 1));
    }
    __syncthreads();

    if (is_last) {
        __threadfence();   // acquire: see all blocks' partials
        double acc = 0.0;
        for (int b = threadIdx.x; b < NBLOCKS_; b += THREADS_)
            acc += g_block_partials[b];
        red_s[threadIdx.x] = acc;
        __syncthreads();
        #pragma unroll
        for (int o = THREADS_ / 2; o; o >>= 1) {
            if (threadIdx.x < o) red_s[threadIdx.x] += red_s[threadIdx.x + o];
            __syncthreads();
        }
        if (threadIdx.x == 0) {
            out[0] = (float)(red_s[0] / (double)N_);
            g_ticket = 0;   // restore for next graph replay
        }
    }
}

extern "C" void kernel_launch(void* const* d_in, const int* in_sizes, int n_in,
                              void* d_out, int out_size) {
    const float* emb    = (const float*)d_in[0];  // output_embedding [N, D] f32
    const float* p      = (const float*)d_in[1];  // input_similarity [N, K] f32
    const int*   anchor = (const int*)d_in[2];    // anchor_idx [N, K] int32
    float* out = (float*)d_out;                   // [0]=loss, [1..]=q row-major

    snl_main_kernel<<<NBLOCKS_, THREADS_>>>(emb, p, anchor, out);
}

// round 5
// speedup vs baseline: 2.6939x; 1.0143x over previous
#include <cuda_runtime.h>

#define N_ 50000
#define K_ 32
#define D_ 128
#define EPS_ 1e-12f
#define WARPS_PER_BLOCK 8
#define THREADS_ (WARPS_PER_BLOCK * 32)
#define NBLOCKS_ ((N_ + WARPS_PER_BLOCK - 1) / WARPS_PER_BLOCK)   // 6250

__device__ double   g_block_partials[NBLOCKS_];
__device__ unsigned g_ticket = 0;   // returns to 0 at end of every run (graph-replay safe)

__global__ __launch_bounds__(THREADS_)
void snl_main_kernel(const float* __restrict__ emb,
                     const float* __restrict__ p,
                     const int* __restrict__ anchor,
                     float* __restrict__ out /* [0]=loss, [1..]=q */) {
    __shared__ double loss_s[WARPS_PER_BLOCK];
    __shared__ double red_s[THREADS_];
    __shared__ bool   is_last;

    const int warp = threadIdx.x >> 5;
    const int lane = threadIdx.x & 31;
    const int i = blockIdx.x * WARPS_PER_BLOCK + warp;   // 6250*8 == 50000 exactly
    float* __restrict__ out_q = out + 1;

    // yi: lane t holds elements [4t, 4t+4) of row i (coalesced 512B load)
    const float4 a = reinterpret_cast<const float4*>(emb + (size_t)i * D_)[lane];

    // lane k owns anchor k's index and p value
    int j_mine = anchor[(size_t)i * K_ + lane];
    j_mine = max(0, min(j_mine, N_ - 1));                // defensive clamp
    const float pv = p[(size_t)i * K_ + lane];

    // v[r] = this lane's 4-dim partial of d2 for anchor r
    float v[K_];
    #pragma unroll
    for (int r = 0; r < K_; r++) {
        const int jr = __shfl_sync(0xffffffffu, j_mine, r);
        // cooperative, fully coalesced 512B row load: lane t takes float4 t
        const float4 b = reinterpret_cast<const float4*>(emb + (size_t)jr * D_)[lane];
        float dx = a.x - b.x;
        float dy = a.y - b.y;
        float dz = a.z - b.z;
        float dw = a.w - b.w;
        float part = dx * dx;
        part = fmaf(dy, dy, part);
        part = fmaf(dz, dz, part);
        part = fmaf(dw, dw, part);
        v[r] = part;
    }

    // Recursive-halving transpose-reduction: 31 shuffles total.
    // After this, lane l holds sum over lanes of original v[l] = d2 for anchor l.
    #pragma unroll
    for (int s = 16; s >= 1; s >>= 1) {
        const bool upper = (lane & s) != 0;
        #pragma unroll
        for (int k = 0; k < s; k++) {
            const float send = upper ? v[k] : v[k + s];
            const float recv = __shfl_xor_sync(0xffffffffu, send, s);
            v[k] = (upper ? v[k + s] : v[k]) + recv;
        }
    }
    const float myd2 = v[0];

    // softmax over K=32 lanes of s = -d2
    const float sc = -myd2;
    float m = sc;
    #pragma unroll
    for (int o = 16; o; o >>= 1) m = fmaxf(m, __shfl_xor_sync(0xffffffffu, m, o));
    const float e = __expf(sc - m);
    float sum = e;
    #pragma unroll
    for (int o = 16; o; o >>= 1) sum += __shfl_xor_sync(0xffffffffu, sum, o);
    const float lse = m + __logf(sum);
    const float logq = sc - lse;
    const float q = __expf(logq);

    out_q[(size_t)i * K_ + lane] = q;

    // KL contribution, warp-reduced
    float contrib = pv * (__logf(pv + EPS_) - logq);
    #pragma unroll
    for (int o = 16; o; o >>= 1) contrib += __shfl_xor_sync(0xffffffffu, contrib, o);
    if (lane == 0) loss_s[warp] = (double)contrib;
    __syncthreads();

    // block partial -> global, take a ticket; last block does the final sum
    if (threadIdx.x == 0) {
        double blk = 0.0;
        #pragma unroll
        for (int w = 0; w < WARPS_PER_BLOCK; w++) blk += loss_s[w];
        g_block_partials[blockIdx.x] = blk;
        __threadfence();
        unsigned t = atomicAdd(&g_ticket, 1u);
        is_last = (t == (unsigned)(NBLOCKS_ - 1));
    }
    __syncthreads();

    if (is_last) {
        __threadfence();   // acquire: see all blocks' partials
        double acc = 0.0;
        for (int b = threadIdx.x; b < NBLOCKS_; b += THREADS_)
            acc += g_block_partials[b];
        red_s[threadIdx.x] = acc;
        __syncthreads();
        #pragma unroll
        for (int o = THREADS_ / 2; o; o >>= 1) {
            if (threadIdx.x < o) red_s[threadIdx.x] += red_s[threadIdx.x + o];
            __syncthreads();
        }
        if (threadIdx.x == 0) {
            out[0] = (float)(red_s[0] / (double)N_);
            g_ticket = 0;   // restore for next graph replay
        }
    }
}

extern "C" void kernel_launch(void* const* d_in, const int* in_sizes, int n_in,
                              void* d_out, int out_size) {
    const float* emb    = (const float*)d_in[0];  // output_embedding [N, D] f32
    const float* p      = (const float*)d_in[1];  // input_similarity [N, K] f32
    const int*   anchor = (const int*)d_in[2];    // anchor_idx [N, K] int32
    float* out = (float*)d_out;                   // [0]=loss, [1..]=q row-major

    snl_main_kernel<<<NBLOCKS_, THREADS_>>>(emb, p, anchor, out);
}

// round 6
// speedup vs baseline: 3.0095x; 1.1172x over previous
#include <cuda_runtime.h>

#define N_ 50000
#define K_ 32
#define D_ 128
#define EPS_ 1e-12f
#define WARPS_PER_BLOCK 8
#define THREADS_ (WARPS_PER_BLOCK * 32)
#define NBLOCKS_ ((N_ + WARPS_PER_BLOCK - 1) / WARPS_PER_BLOCK)   // 6250

__device__ double   g_block_partials[NBLOCKS_];
__device__ unsigned g_ticket = 0;   // returns to 0 at end of every run (graph-replay safe)

__global__ __launch_bounds__(THREADS_)
void snl_main_kernel(const float* __restrict__ emb,
                     const float* __restrict__ p,
                     const int* __restrict__ anchor,
                     float* __restrict__ out /* [0]=loss, [1..]=q */) {
    __shared__ double loss_s[WARPS_PER_BLOCK];
    __shared__ double red_s[THREADS_];
    __shared__ bool   is_last;

    const int warp = threadIdx.x >> 5;
    const int lane = threadIdx.x & 31;
    const int i = blockIdx.x * WARPS_PER_BLOCK + warp;   // 6250*8 == 50000 exactly
    float* __restrict__ out_q = out + 1;

    // yi: lane t holds elements [4t, 4t+4) of row i (coalesced 512B load)
    const float4 a = reinterpret_cast<const float4*>(emb + (size_t)i * D_)[lane];

    // lane k owns anchor k's index (identity layout, used only for broadcasts)
    int j_mine = anchor[(size_t)i * K_ + lane];
    j_mine = max(0, min(j_mine, N_ - 1));                // defensive clamp

    const bool hi_half = (lane & 16) != 0;

    // Pairwise-folded partials: w[t] holds (low lanes: anchor 2t, high lanes: anchor 2t+1),
    // each already summed over lane-pairs (l, l^16). Only 16 live registers.
    float w[K_ / 2];
    #pragma unroll
    for (int t = 0; t < K_ / 2; t++) {
        const int jr0 = __shfl_sync(0xffffffffu, j_mine, 2 * t);
        const int jr1 = __shfl_sync(0xffffffffu, j_mine, 2 * t + 1);
        const float4 b0 = reinterpret_cast<const float4*>(emb + (size_t)jr0 * D_)[lane];
        const float4 b1 = reinterpret_cast<const float4*>(emb + (size_t)jr1 * D_)[lane];

        float dx = a.x - b0.x, dy = a.y - b0.y, dz = a.z - b0.z, dw = a.w - b0.w;
        float part0 = dx * dx;
        part0 = fmaf(dy, dy, part0);
        part0 = fmaf(dz, dz, part0);
        part0 = fmaf(dw, dw, part0);

        dx = a.x - b1.x; dy = a.y - b1.y; dz = a.z - b1.z; dw = a.w - b1.w;
        float part1 = dx * dx;
        part1 = fmaf(dy, dy, part1);
        part1 = fmaf(dz, dz, part1);
        part1 = fmaf(dw, dw, part1);

        // fold: low half keeps anchor 2t, high half keeps anchor 2t+1
        const float send = hi_half ? part0 : part1;
        const float recv = __shfl_xor_sync(0xffffffffu, send, 16);
        w[t] = (hi_half ? part1 : part0) + recv;
    }

    // Recursive halving on 16 values (exchanges stay within each half-warp):
    // 15 shuffles; lane l ends with d2 for anchor a(l) = 2*(l&15) + (l>>4).
    #pragma unroll
    for (int s = 8; s >= 1; s >>= 1) {
        const bool upper = (lane & s) != 0;
        #pragma unroll
        for (int k = 0; k < s; k++) {
            const float send = upper ? w[k] : w[k + s];
            const float recv = __shfl_xor_sync(0xffffffffu, send, s);
            w[k] = (upper ? w[k + s] : w[k]) + recv;
        }
    }
    const float myd2 = w[0];
    const int   acol = 2 * (lane & 15) + (lane >> 4);   // anchor owned by this lane

    // softmax over the 32 lanes (each lane holds a distinct anchor's score)
    const float sc = -myd2;
    float m = sc;
    #pragma unroll
    for (int o = 16; o; o >>= 1) m = fmaxf(m, __shfl_xor_sync(0xffffffffu, m, o));
    const float e = __expf(sc - m);
    float sum = e;
    #pragma unroll
    for (int o = 16; o; o >>= 1) sum += __shfl_xor_sync(0xffffffffu, sum, o);
    const float lse = m + __logf(sum);
    const float logq = sc - lse;
    const float q = __expf(logq);

    // permuted-column accesses stay inside one 128B row: still one wavefront
    const float pv = p[(size_t)i * K_ + acol];
    out_q[(size_t)i * K_ + acol] = q;

    // KL contribution, warp-reduced
    float contrib = pv * (__logf(pv + EPS_) - logq);
    #pragma unroll
    for (int o = 16; o; o >>= 1) contrib += __shfl_xor_sync(0xffffffffu, contrib, o);
    if (lane == 0) loss_s[warp] = (double)contrib;
    __syncthreads();

    // block partial -> global, take a ticket; last block does the final sum
    if (threadIdx.x == 0) {
        double blk = 0.0;
        #pragma unroll
        for (int w2 = 0; w2 < WARPS_PER_BLOCK; w2++) blk += loss_s[w2];
        g_block_partials[blockIdx.x] = blk;
        __threadfence();
        unsigned t = atomicAdd(&g_ticket, 1u);
        is_last = (t == (unsigned)(NBLOCKS_ - 1));
    }
    __syncthreads();

    if (is_last) {
        __threadfence();   // acquire: see all blocks' partials
        double acc = 0.0;
        for (int b = threadIdx.x; b < NBLOCKS_; b += THREADS_)
            acc += g_block_partials[b];
        red_s[threadIdx.x] = acc;
        __syncthreads();
        #pragma unroll
        for (int o = THREADS_ / 2; o; o >>= 1) {
            if (threadIdx.x < o) red_s[threadIdx.x] += red_s[threadIdx.x + o];
            __syncthreads();
        }
        if (threadIdx.x == 0) {
            out[0] = (float)(red_s[0] / (double)N_);
            g_ticket = 0;   // restore for next graph replay
        }
    }
}

extern "C" void kernel_launch(void* const* d_in, const int* in_sizes, int n_in,
                              void* d_out, int out_size) {
    const float* emb    = (const float*)d_in[0];  // output_embedding [N, D] f32
    const float* p      = (const float*)d_in[1];  // input_similarity [N, K] f32
    const int*   anchor = (const int*)d_in[2];    // anchor_idx [N, K] int32
    float* out = (float*)d_out;                   // [0]=loss, [1..]=q row-major

    snl_main_kernel<<<NBLOCKS_, THREADS_>>>(emb, p, anchor, out);
}

// round 7
// speedup vs baseline: 3.1043x; 1.0315x over previous
#include <cuda_runtime.h>

#define N_ 50000
#define K_ 32
#define D_ 128
#define EPS_ 1e-12f
#define WARPS_PER_BLOCK 8
#define THREADS_ (WARPS_PER_BLOCK * 32)
#define NBLOCKS_ ((N_ + WARPS_PER_BLOCK - 1) / WARPS_PER_BLOCK)   // 6250

__device__ double   g_block_partials[NBLOCKS_];
__device__ unsigned g_ticket = 0;   // returns to 0 at end of every run (graph-replay safe)

__global__ __launch_bounds__(THREADS_, 6)
void snl_main_kernel(const float* __restrict__ emb,
                     const float* __restrict__ p,
                     const int* __restrict__ anchor,
                     float* __restrict__ out /* [0]=loss, [1..]=q */) {
    __shared__ double loss_s[WARPS_PER_BLOCK];
    __shared__ double red_s[THREADS_];
    __shared__ bool   is_last;

    const int warp = threadIdx.x >> 5;
    const int lane = threadIdx.x & 31;
    const int i = blockIdx.x * WARPS_PER_BLOCK + warp;   // 6250*8 == 50000 exactly
    float* __restrict__ out_q = out + 1;

    // yi: lane t holds elements [4t, 4t+4) of row i (coalesced 512B load)
    const float4 a = reinterpret_cast<const float4*>(emb + (size_t)i * D_)[lane];

    // lane k owns anchor k's index (identity layout; used only for broadcasts)
    int j_mine = anchor[(size_t)i * K_ + lane];
    j_mine = max(0, min(j_mine, N_ - 1));                // defensive clamp

    const bool hi16 = (lane & 16) != 0;
    const bool hi8  = (lane & 8) != 0;

    // 4-way folded partials: w[g] covers anchors 4g..4g+3.
    // After the two folds, lane l's w[g] = partial of anchor (4g + 2*b8 + b16),
    // already summed over lane-quad {l, l^8, l^16, l^24}.
    float w[K_ / 4];
    #pragma unroll
    for (int g = 0; g < K_ / 4; g++) {
        const int jr0 = __shfl_sync(0xffffffffu, j_mine, 4 * g);
        const int jr1 = __shfl_sync(0xffffffffu, j_mine, 4 * g + 1);
        const int jr2 = __shfl_sync(0xffffffffu, j_mine, 4 * g + 2);
        const int jr3 = __shfl_sync(0xffffffffu, j_mine, 4 * g + 3);
        const float4 b0 = reinterpret_cast<const float4*>(emb + (size_t)jr0 * D_)[lane];
        const float4 b1 = reinterpret_cast<const float4*>(emb + (size_t)jr1 * D_)[lane];
        const float4 b2 = reinterpret_cast<const float4*>(emb + (size_t)jr2 * D_)[lane];
        const float4 b3 = reinterpret_cast<const float4*>(emb + (size_t)jr3 * D_)[lane];

        float dx = a.x - b0.x, dy = a.y - b0.y, dz = a.z - b0.z, dw = a.w - b0.w;
        float p0 = dx * dx; p0 = fmaf(dy, dy, p0); p0 = fmaf(dz, dz, p0); p0 = fmaf(dw, dw, p0);
        dx = a.x - b1.x; dy = a.y - b1.y; dz = a.z - b1.z; dw = a.w - b1.w;
        float p1 = dx * dx; p1 = fmaf(dy, dy, p1); p1 = fmaf(dz, dz, p1); p1 = fmaf(dw, dw, p1);
        dx = a.x - b2.x; dy = a.y - b2.y; dz = a.z - b2.z; dw = a.w - b2.w;
        float p2 = dx * dx; p2 = fmaf(dy, dy, p2); p2 = fmaf(dz, dz, p2); p2 = fmaf(dw, dw, p2);
        dx = a.x - b3.x; dy = a.y - b3.y; dz = a.z - b3.z; dw = a.w - b3.w;
        float p3 = dx * dx; p3 = fmaf(dy, dy, p3); p3 = fmaf(dz, dz, p3); p3 = fmaf(dw, dw, p3);

        // fold pairs across xor-16: low16 keeps even anchor, high16 keeps odd
        float s01 = hi16 ? p0 : p1;
        float u01 = (hi16 ? p1 : p0) + __shfl_xor_sync(0xffffffffu, s01, 16);
        float s23 = hi16 ? p2 : p3;
        float u23 = (hi16 ? p3 : p2) + __shfl_xor_sync(0xffffffffu, s23, 16);
        // fold across xor-8: bit8=0 keeps u01, bit8=1 keeps u23
        float s8 = hi8 ? u01 : u23;
        w[g] = (hi8 ? u23 : u01) + __shfl_xor_sync(0xffffffffu, s8, 8);
    }

    // Recursive halving on 8 values (within each 8-lane group): 7 shuffles.
    #pragma unroll
    for (int s = 4; s >= 1; s >>= 1) {
        const bool upper = (lane & s) != 0;
        #pragma unroll
        for (int k = 0; k < s; k++) {
            const float send = upper ? w[k] : w[k + s];
            const float recv = __shfl_xor_sync(0xffffffffu, send, s);
            w[k] = (upper ? w[k + s] : w[k]) + recv;
        }
    }
    const float myd2 = w[0];
    // anchor owned by lane l
    const int acol = 4 * (lane & 7) + 2 * ((lane >> 3) & 1) + ((lane >> 4) & 1);

    // softmax over the 32 lanes (each lane holds a distinct anchor's score)
    const float sc = -myd2;
    float m = sc;
    #pragma unroll
    for (int o = 16; o; o >>= 1) m = fmaxf(m, __shfl_xor_sync(0xffffffffu, m, o));
    const float e = __expf(sc - m);
    float sum = e;
    #pragma unroll
    for (int o = 16; o; o >>= 1) sum += __shfl_xor_sync(0xffffffffu, sum, o);
    const float lse = m + __logf(sum);
    const float logq = sc - lse;
    const float q = __expf(logq);

    // permuted-column accesses stay inside one 128B row: still one wavefront
    const float pv = p[(size_t)i * K_ + acol];
    out_q[(size_t)i * K_ + acol] = q;

    // KL contribution, warp-reduced
    float contrib = pv * (__logf(pv + EPS_) - logq);
    #pragma unroll
    for (int o = 16; o; o >>= 1) contrib += __shfl_xor_sync(0xffffffffu, contrib, o);
    if (lane == 0) loss_s[warp] = (double)contrib;
    __syncthreads();

    // block partial -> global, take a ticket; last block does the final sum
    if (threadIdx.x == 0) {
        double blk = 0.0;
        #pragma unroll
        for (int w2 = 0; w2 < WARPS_PER_BLOCK; w2++) blk += loss_s[w2];
        g_block_partials[blockIdx.x] = blk;
        __threadfence();
        unsigned t = atomicAdd(&g_ticket, 1u);
        is_last = (t == (unsigned)(NBLOCKS_ - 1));
    }
    __syncthreads();

    if (is_last) {
        __threadfence();   // acquire: see all blocks' partials
        double acc = 0.0;
        for (int b = threadIdx.x; b < NBLOCKS_; b += THREADS_)
            acc += g_block_partials[b];
        red_s[threadIdx.x] = acc;
        __syncthreads();
        #pragma unroll
        for (int o = THREADS_ / 2; o; o >>= 1) {
            if (threadIdx.x < o) red_s[threadIdx.x] += red_s[threadIdx.x + o];
            __syncthreads();
        }
        if (threadIdx.x == 0) {
            out[0] = (float)(red_s[0] / (double)N_);
            g_ticket = 0;   // restore for next graph replay
        }
    }
}

extern "C" void kernel_launch(void* const* d_in, const int* in_sizes, int n_in,
                              void* d_out, int out_size) {
    const float* emb    = (const float*)d_in[0];  // output_embedding [N, D] f32
    const float* p      = (const float*)d_in[1];  // input_similarity [N, K] f32
    const int*   anchor = (const int*)d_in[2];    // anchor_idx [N, K] int32
    float* out = (float*)d_out;                   // [0]=loss, [1..]=q row-major

    snl_main_kernel<<<NBLOCKS_, THREADS_>>>(emb, p, anchor, out);
}